// round 1
// baseline (speedup 1.0000x reference)
#include <cuda_runtime.h>
#include <cstdint>

#define NUM_NODES 1000000
#define DIM 128
#define VEC 32          // DIM/4 float4 per row
#define BATCH 262144
#define MOM 0.9f
#define OMM 0.1f        // 1 - momentum

// Scratch: last-occurrence winner per node (deterministic duplicate resolution).
__device__ int g_winner[NUM_NODES];

__global__ void init_winner_kernel() {
    int i = blockIdx.x * blockDim.x + threadIdx.x;
    if (i < NUM_NODES) g_winner[i] = -1;
}

__global__ void mark_winner_kernel(const int* __restrict__ idx) {
    int i = blockIdx.x * blockDim.x + threadIdx.x;
    if (i < BATCH) atomicMax(&g_winner[idx[i]], i);
}

// Copy memory/variance -> new_memory/new_variance, skipping rows that the
// batch kernel will overwrite (winner >= 0). One thread per float4.
__global__ void copy_state_kernel(const float4* __restrict__ mem,
                                  const float4* __restrict__ var,
                                  float4* __restrict__ out_mem,
                                  float4* __restrict__ out_var) {
    long long t = (long long)blockIdx.x * blockDim.x + threadIdx.x;
    const long long total = (long long)NUM_NODES * VEC;
    if (t >= total) return;
    int node = (int)(t >> 5);                // t / VEC
    if (g_winner[node] >= 0) return;         // scatter kernel owns this row
    out_mem[t] = mem[t];
    out_var[t] = var[t];
}

// One warp (32 threads) per batch row; each thread owns one float4 (4 dims).
__global__ void batch_update_kernel(const int* __restrict__ idx,
                                    const float4* __restrict__ values,
                                    const float4* __restrict__ mem,
                                    const float4* __restrict__ var,
                                    float4* __restrict__ mem_read,
                                    float4* __restrict__ var_read,
                                    float4* __restrict__ out_mem,
                                    float4* __restrict__ out_var) {
    long long t = (long long)blockIdx.x * blockDim.x + threadIdx.x;
    const long long total = (long long)BATCH * VEC;
    if (t >= total) return;
    int i    = (int)(t >> 5);                // batch row
    int lane = (int)(t & 31);                // float4 within row
    int node = __ldg(&idx[i]);
    long long src = (long long)node * VEC + lane;

    float4 mv  = mem[src];
    float4 vv  = var[src];
    float4 val = values[t];

    mem_read[t] = mv;
    var_read[t] = vv;

    float4 d;
    d.x = val.x - mv.x; d.y = val.y - mv.y;
    d.z = val.z - mv.z; d.w = val.w - mv.w;

    float4 nm, nv;
    nm.x = MOM * mv.x + OMM * val.x;
    nm.y = MOM * mv.y + OMM * val.y;
    nm.z = MOM * mv.z + OMM * val.z;
    nm.w = MOM * mv.w + OMM * val.w;

    nv.x = MOM * vv.x + OMM * d.x * d.x;
    nv.y = MOM * vv.y + OMM * d.y * d.y;
    nv.z = MOM * vv.z + OMM * d.z * d.z;
    nv.w = MOM * vv.w + OMM * d.w * d.w;

    if (g_winner[node] == i) {               // last occurrence wins
        out_mem[src] = nm;
        out_var[src] = nv;
    }
}

extern "C" void kernel_launch(void* const* d_in, const int* in_sizes, int n_in,
                              void* d_out, int out_size) {
    const int*    idx    = (const int*)   d_in[0];
    const float4* values = (const float4*)d_in[1];
    const float4* mem    = (const float4*)d_in[2];
    const float4* var    = (const float4*)d_in[3];

    float* out = (float*)d_out;
    float4* mem_read = (float4*)out;                                    // [B, D]
    float4* var_read = (float4*)(out + (size_t)BATCH * DIM);            // [B, D]
    float4* out_mem  = (float4*)(out + 2ull * BATCH * DIM);             // [N, D]
    float4* out_var  = (float4*)(out + 2ull * BATCH * DIM
                                     + (size_t)NUM_NODES * DIM);        // [N, D]

    {
        int threads = 256;
        int blocks = (NUM_NODES + threads - 1) / threads;
        init_winner_kernel<<<blocks, threads>>>();
    }
    {
        int threads = 256;
        int blocks = (BATCH + threads - 1) / threads;
        mark_winner_kernel<<<blocks, threads>>>(idx);
    }
    {
        long long total = (long long)NUM_NODES * VEC;   // 32,000,000
        int threads = 256;
        long long blocks = (total + threads - 1) / threads;
        copy_state_kernel<<<(unsigned)blocks, threads>>>(mem, var, out_mem, out_var);
    }
    {
        long long total = (long long)BATCH * VEC;       // 8,388,608
        int threads = 256;
        long long blocks = (total + threads - 1) / threads;
        batch_update_kernel<<<(unsigned)blocks, threads>>>(
            idx, values, mem, var, mem_read, var_read, out_mem, out_var);
    }
}

// round 2
// speedup vs baseline: 1.0233x; 1.0233x over previous
#include <cuda_runtime.h>
#include <cstdint>

#define NUM_NODES 1000000
#define DIM 128
#define VEC 32          // DIM/4 float4 per row
#define BATCH 262144
#define MOM 0.9f
#define OMM 0.1f        // 1 - momentum

// Scratch: last-occurrence winner per node (deterministic duplicate resolution).
__device__ int g_winner[NUM_NODES];

__global__ void init_winner_kernel() {
    int i = blockIdx.x * blockDim.x + threadIdx.x;
    if (i < NUM_NODES) g_winner[i] = -1;
}

__global__ void mark_winner_kernel(const int* __restrict__ idx) {
    int i = blockIdx.x * blockDim.x + threadIdx.x;
    if (i < BATCH) atomicMax(&g_winner[idx[i]], i);
}

// Copy memory/variance -> new_memory/new_variance, skipping rows the batch
// kernel will overwrite. 2 float4-slots per thread (split halves of the
// tensor) for deeper MLP. Streaming loads/stores: data is touched once.
__global__ void copy_state_kernel(const float4* __restrict__ mem,
                                  const float4* __restrict__ var,
                                  float4* __restrict__ out_mem,
                                  float4* __restrict__ out_var) {
    const long long half = (long long)NUM_NODES * VEC / 2;   // 16,000,000
    long long t = (long long)blockIdx.x * blockDim.x + threadIdx.x;
    if (t >= half) return;
    long long t2 = t + half;
    int node1 = (int)(t  >> 5);
    int node2 = (int)(t2 >> 5);
    bool do1 = (g_winner[node1] < 0);
    bool do2 = (g_winner[node2] < 0);
    float4 m1, v1, m2, v2;
    if (do1) { m1 = __ldcs(&mem[t]);  v1 = __ldcs(&var[t]);  }
    if (do2) { m2 = __ldcs(&mem[t2]); v2 = __ldcs(&var[t2]); }
    if (do1) { __stcs(&out_mem[t],  m1); __stcs(&out_var[t],  v1); }
    if (do2) { __stcs(&out_mem[t2], m2); __stcs(&out_var[t2], v2); }
}

// One warp (32 threads) per batch row; each thread owns one float4 (4 dims).
__global__ void batch_update_kernel(const int* __restrict__ idx,
                                    const float4* __restrict__ values,
                                    const float4* __restrict__ mem,
                                    const float4* __restrict__ var,
                                    float4* __restrict__ mem_read,
                                    float4* __restrict__ var_read,
                                    float4* __restrict__ out_mem,
                                    float4* __restrict__ out_var) {
    long long t = (long long)blockIdx.x * blockDim.x + threadIdx.x;
    const long long total = (long long)BATCH * VEC;
    if (t >= total) return;
    int i    = (int)(t >> 5);                // batch row (uniform per warp)
    int lane = (int)(t & 31);
    int node = __ldg(&idx[i]);
    long long src = (long long)node * VEC + lane;

    // Gather: default cache policy (duplicate idx rows reuse L2).
    float4 mv  = mem[src];
    float4 vv  = var[src];
    float4 val = __ldcs(&values[t]);

    __stcs(&mem_read[t], mv);
    __stcs(&var_read[t], vv);

    float4 d;
    d.x = val.x - mv.x; d.y = val.y - mv.y;
    d.z = val.z - mv.z; d.w = val.w - mv.w;

    float4 nm, nv;
    nm.x = MOM * mv.x + OMM * val.x;
    nm.y = MOM * mv.y + OMM * val.y;
    nm.z = MOM * mv.z + OMM * val.z;
    nm.w = MOM * mv.w + OMM * val.w;

    nv.x = MOM * vv.x + OMM * d.x * d.x;
    nv.y = MOM * vv.y + OMM * d.y * d.y;
    nv.z = MOM * vv.z + OMM * d.z * d.z;
    nv.w = MOM * vv.w + OMM * d.w * d.w;

    if (g_winner[node] == i) {               // last occurrence wins
        __stcs(&out_mem[src], nm);
        __stcs(&out_var[src], nv);
    }
}

extern "C" void kernel_launch(void* const* d_in, const int* in_sizes, int n_in,
                              void* d_out, int out_size) {
    const int*    idx    = (const int*)   d_in[0];
    const float4* values = (const float4*)d_in[1];
    const float4* mem    = (const float4*)d_in[2];
    const float4* var    = (const float4*)d_in[3];

    float* out = (float*)d_out;
    float4* mem_read = (float4*)out;                                    // [B, D]
    float4* var_read = (float4*)(out + (size_t)BATCH * DIM);            // [B, D]
    float4* out_mem  = (float4*)(out + 2ull * BATCH * DIM);             // [N, D]
    float4* out_var  = (float4*)(out + 2ull * BATCH * DIM
                                     + (size_t)NUM_NODES * DIM);        // [N, D]

    {
        int threads = 256;
        int blocks = (NUM_NODES + threads - 1) / threads;
        init_winner_kernel<<<blocks, threads>>>();
    }
    {
        int threads = 256;
        int blocks = (BATCH + threads - 1) / threads;
        mark_winner_kernel<<<blocks, threads>>>(idx);
    }
    {
        long long half = (long long)NUM_NODES * VEC / 2;   // 16,000,000
        int threads = 256;
        long long blocks = (half + threads - 1) / threads;
        copy_state_kernel<<<(unsigned)blocks, threads>>>(mem, var, out_mem, out_var);
    }
    {
        long long total = (long long)BATCH * VEC;          // 8,388,608
        int threads = 256;
        long long blocks = (total + threads - 1) / threads;
        batch_update_kernel<<<(unsigned)blocks, threads>>>(
            idx, values, mem, var, mem_read, var_read, out_mem, out_var);
    }
}

// round 3
// speedup vs baseline: 1.0247x; 1.0014x over previous
#include <cuda_runtime.h>
#include <cstdint>

#define NUM_NODES 1000000
#define DIM 128
#define VEC 32          // DIM/4 float4 per row
#define BATCH 262144
#define MOM 0.9f
#define OMM 0.1f        // 1 - momentum

// Scratch: last-occurrence winner per node (deterministic duplicate resolution).
__device__ int g_winner[NUM_NODES];

__global__ void init_winner_kernel() {
    int i = blockIdx.x * blockDim.x + threadIdx.x;
    if (i < NUM_NODES) g_winner[i] = -1;
}

__global__ void mark_winner_kernel(const int* __restrict__ idx) {
    int i = blockIdx.x * blockDim.x + threadIdx.x;
    if (i < BATCH) atomicMax(&g_winner[idx[i]], i);
}

// ---- fused batch-update + state-copy -------------------------------------
// Index space:
//   [0, BHALF)           : batch path, 2 rows-worth of float4 per thread
//   [BHALF, BHALF+CHALF) : copy path,  2 float4 per thread (split halves)

#define BITEMS   ((long long)BATCH * VEC)        // 8,388,608
#define BHALF    (BITEMS / 2)                    // 4,194,304 threads
#define CITEMS   ((long long)NUM_NODES * VEC)    // 32,000,000
#define CHALF    (CITEMS / 2)                    // 16,000,000 threads

__device__ __forceinline__ void batch_item(long long t,
                                           const int* __restrict__ idx,
                                           const float4* __restrict__ values,
                                           const float4* __restrict__ mem,
                                           const float4* __restrict__ var,
                                           float4* __restrict__ mem_read,
                                           float4* __restrict__ var_read,
                                           float4* __restrict__ out_mem,
                                           float4* __restrict__ out_var) {
    int i    = (int)(t >> 5);                // batch row (uniform per warp)
    int lane = (int)(t & 31);
    int node = __ldg(&idx[i]);
    long long src = (long long)node * VEC + lane;

    float4 mv  = mem[src];                   // default policy: dup rows hit L2
    float4 vv  = var[src];
    float4 val = __ldcs(&values[t]);

    __stcs(&mem_read[t], mv);
    __stcs(&var_read[t], vv);

    float4 d, nm, nv;
    d.x = val.x - mv.x; d.y = val.y - mv.y;
    d.z = val.z - mv.z; d.w = val.w - mv.w;
    nm.x = MOM * mv.x + OMM * val.x;
    nm.y = MOM * mv.y + OMM * val.y;
    nm.z = MOM * mv.z + OMM * val.z;
    nm.w = MOM * mv.w + OMM * val.w;
    nv.x = MOM * vv.x + OMM * d.x * d.x;
    nv.y = MOM * vv.y + OMM * d.y * d.y;
    nv.z = MOM * vv.z + OMM * d.z * d.z;
    nv.w = MOM * vv.w + OMM * d.w * d.w;

    if (g_winner[node] == i) {               // last occurrence wins
        __stcs(&out_mem[src], nm);
        __stcs(&out_var[src], nv);
    }
}

__global__ void fused_kernel(const int* __restrict__ idx,
                             const float4* __restrict__ values,
                             const float4* __restrict__ mem,
                             const float4* __restrict__ var,
                             float4* __restrict__ mem_read,
                             float4* __restrict__ var_read,
                             float4* __restrict__ out_mem,
                             float4* __restrict__ out_var) {
    long long t = (long long)blockIdx.x * blockDim.x + threadIdx.x;
    if (t < BHALF) {
        // ---- batch path: two independent rows per thread (2x MLP) ----
        batch_item(t,         idx, values, mem, var, mem_read, var_read, out_mem, out_var);
        batch_item(t + BHALF, idx, values, mem, var, mem_read, var_read, out_mem, out_var);
    } else {
        // ---- copy path: two float4 per thread, split halves ----
        long long c = t - BHALF;
        if (c >= CHALF) return;
        long long c2 = c + CHALF;
        int node1 = (int)(c  >> 5);
        int node2 = (int)(c2 >> 5);
        bool do1 = (g_winner[node1] < 0);
        bool do2 = (g_winner[node2] < 0);
        float4 m1, v1, m2, v2;
        if (do1) { m1 = __ldcs(&mem[c]);  v1 = __ldcs(&var[c]);  }
        if (do2) { m2 = __ldcs(&mem[c2]); v2 = __ldcs(&var[c2]); }
        if (do1) { __stcs(&out_mem[c],  m1); __stcs(&out_var[c],  v1); }
        if (do2) { __stcs(&out_mem[c2], m2); __stcs(&out_var[c2], v2); }
    }
}

extern "C" void kernel_launch(void* const* d_in, const int* in_sizes, int n_in,
                              void* d_out, int out_size) {
    const int*    idx    = (const int*)   d_in[0];
    const float4* values = (const float4*)d_in[1];
    const float4* mem    = (const float4*)d_in[2];
    const float4* var    = (const float4*)d_in[3];

    float* out = (float*)d_out;
    float4* mem_read = (float4*)out;                                    // [B, D]
    float4* var_read = (float4*)(out + (size_t)BATCH * DIM);            // [B, D]
    float4* out_mem  = (float4*)(out + 2ull * BATCH * DIM);             // [N, D]
    float4* out_var  = (float4*)(out + 2ull * BATCH * DIM
                                     + (size_t)NUM_NODES * DIM);        // [N, D]

    {
        int threads = 256;
        int blocks = (NUM_NODES + threads - 1) / threads;
        init_winner_kernel<<<blocks, threads>>>();
    }
    {
        int threads = 256;
        int blocks = (BATCH + threads - 1) / threads;
        mark_winner_kernel<<<blocks, threads>>>(idx);
    }
    {
        long long total_threads = BHALF + CHALF;   // 20,194,304
        int threads = 256;
        long long blocks = (total_threads + threads - 1) / threads;
        fused_kernel<<<(unsigned)blocks, threads>>>(
            idx, values, mem, var, mem_read, var_read, out_mem, out_var);
    }
}